// round 1
// baseline (speedup 1.0000x reference)
#include <cuda_runtime.h>

// Unfold (im2col): x[16,96,56,56] f32, kernel 3x3, pad 1
// out[b, c*9 + ki*3+kj, h*56+w] = x_padded[b, c, h+ki, w+kj]
// Pure memory-movement kernel: one float4 store per thread, fully coalesced.

#define B_ 16
#define C_ 96
#define H_ 56
#define W_ 56
#define HW_ (H_ * W_)       // 3136
#define HW4_ (HW_ / 4)      // 784
#define TOTAL4_ (B_ * C_ * 9 * HW4_)  // 10,838,016

__global__ __launch_bounds__(256) void unfold_kernel(
    const float* __restrict__ x, float* __restrict__ out)
{
    int tid = blockIdx.x * blockDim.x + threadIdx.x;
    if (tid >= TOTAL4_) return;

    // tid = ((bc*9 + k) * HW4_) + p4
    int p4   = tid % HW4_;
    int rest = tid / HW4_;
    int k    = rest % 9;        // ki*3 + kj
    int bc   = rest / 9;        // b*C_ + c

    int ki = k / 3;
    int kj = k % 3;

    int p = p4 * 4;
    int h = p / W_;
    int w = p - h * W_;         // multiple of 4, so all 4 elems share row h

    int sh = h + ki - 1;        // source row in unpadded image
    float4 v = make_float4(0.f, 0.f, 0.f, 0.f);

    if (sh >= 0 && sh < H_) {
        const float* row = x + ((long)bc * H_ + sh) * W_;
        int sw = w + kj - 1;    // leftmost source col (may be -1 or reach 56)
        float vals[4];
        #pragma unroll
        for (int i = 0; i < 4; i++) {
            int c = sw + i;
            vals[i] = (c >= 0 && c < W_) ? __ldg(row + c) : 0.f;
        }
        v = make_float4(vals[0], vals[1], vals[2], vals[3]);
    }

    reinterpret_cast<float4*>(out)[tid] = v;
}

extern "C" void kernel_launch(void* const* d_in, const int* in_sizes, int n_in,
                              void* d_out, int out_size)
{
    const float* x = (const float*)d_in[0];
    float* out = (float*)d_out;
    int blocks = (TOTAL4_ + 255) / 256;   // 42336, exact
    unfold_kernel<<<blocks, 256>>>(x, out);
}

// round 2
// speedup vs baseline: 1.6667x; 1.6667x over previous
#include <cuda_runtime.h>

// Unfold (im2col): x[16,96,56,56] f32, 3x3 window, pad 1
// out[bc*9 + ki*3+kj][h*56+w] = x_pad[bc][h+ki][w+kj]
//
// One thread = one (bc, h, w4) position, produces all 9 window outputs:
//   loads 3 rows (1 LDG.128 + 2 edge scalars each), stages 18 floats,
//   emits 9 STG.128 streaming stores. Load instrs 4x fewer than v1,
//   index math amortized 9x.

#define B_ 16
#define C_ 96
#define H_ 56
#define W_ 56
#define HW_ (H_ * W_)        // 3136
#define HW4_ (HW_ / 4)       // 784
#define NTHREADS_ (B_ * C_ * HW4_)   // 1,204,224 = 4704 * 256 exactly

__global__ __launch_bounds__(256) void unfold_kernel(
    const float* __restrict__ x, float* __restrict__ out)
{
    int tid = blockIdx.x * 256 + threadIdx.x;   // grid is exact, no guard

    int p4 = tid % HW4_;
    int bc = tid / HW4_;
    int p  = p4 * 4;
    int h  = p / W_;
    int w  = p - h * W_;      // multiple of 4

    const float* base = x + (size_t)bc * HW_;

    // Stage 3 rows x 6 cols: [w-1, w, w+1, w+2, w+3, w+4]
    float rv[3][6];
    #pragma unroll
    for (int r = 0; r < 3; r++) {
        int sh = h + r - 1;
        if (sh >= 0 && sh < H_) {
            const float* rp = base + sh * W_;
            float4 m = *reinterpret_cast<const float4*>(rp + w);   // aligned
            rv[r][1] = m.x; rv[r][2] = m.y; rv[r][3] = m.z; rv[r][4] = m.w;
            rv[r][0] = (w > 0)        ? __ldg(rp + w - 1) : 0.f;
            rv[r][5] = (w + 4 < W_)   ? __ldg(rp + w + 4) : 0.f;
        } else {
            #pragma unroll
            for (int i = 0; i < 6; i++) rv[r][i] = 0.f;
        }
    }

    // 9 streaming stores: out[(bc*9 + r*3+kj)*HW_ + p .. +3]
    float* obase = out + (size_t)bc * 9 * HW_ + p;
    #pragma unroll
    for (int r = 0; r < 3; r++) {
        #pragma unroll
        for (int kj = 0; kj < 3; kj++) {
            float4 v = make_float4(rv[r][kj], rv[r][kj + 1],
                                   rv[r][kj + 2], rv[r][kj + 3]);
            __stcs(reinterpret_cast<float4*>(obase + (r * 3 + kj) * HW_), v);
        }
    }
}

extern "C" void kernel_launch(void* const* d_in, const int* in_sizes, int n_in,
                              void* d_out, int out_size)
{
    const float* x = (const float*)d_in[0];
    float* out = (float*)d_out;
    unfold_kernel<<<NTHREADS_ / 256, 256>>>(x, out);
}